// round 6
// baseline (speedup 1.0000x reference)
#include <cuda_runtime.h>
#include <cstdint>

// Problem constants (fixed by the reference: N=8192, D=4096, E=64, K=2)
#define N_ROWS   8192
#define DIM      4096
#define NEXP     64
#define TOPK     2

// Tiling
#define TM       64            // rows per CTA
#define KT       32            // k-tile depth
#define XS_STRIDE 36           // 32 + 4 pad (keeps float4 alignment, dodges bank conflicts)
#define THREADS  256
#define NTILES   (DIM / KT)    // 128

// ---------------------------------------------------------------------------
// PTX helpers
// ---------------------------------------------------------------------------
__device__ __forceinline__ void fma2(unsigned long long& acc,
                                     unsigned long long a,
                                     unsigned long long b) {
    // packed f32x2 FMA: acc.lo += a.lo*b.lo ; acc.hi += a.hi*b.hi
    asm volatile("fma.rn.f32x2 %0, %1, %2, %0;" : "+l"(acc) : "l"(a), "l"(b));
}

__device__ __forceinline__ void cp16(uint32_t smem_addr, const void* gptr) {
    asm volatile("cp.async.ca.shared.global [%0], [%1], 16;"
                 :: "r"(smem_addr), "l"(gptr));
}
__device__ __forceinline__ void cp_commit() {
    asm volatile("cp.async.commit_group;");
}
template <int N>
__device__ __forceinline__ void cp_wait() {
    asm volatile("cp.async.wait_group %0;" :: "n"(N));
}

__device__ __forceinline__ uint32_t smem_u32(const void* p) {
    uint32_t r;
    asm("{ .reg .u64 t; cvta.to.shared.u64 t, %1; cvt.u32.u64 %0, t; }"
        : "=r"(r) : "l"(p));
    return r;
}

__device__ __forceinline__ float u64_lo(unsigned long long a) {
    return __uint_as_float((uint32_t)(a & 0xffffffffull));
}
__device__ __forceinline__ float u64_hi(unsigned long long a) {
    return __uint_as_float((uint32_t)(a >> 32));
}

// ---------------------------------------------------------------------------
// Fused kernel: logits GEMM (fp32, FFMA2) + bias + softmax + top-2
// out layout: [0 : N*K)          top-2 indices (as float)
//             [N*K : 2*N*K)      top-2 softmax weights
// ---------------------------------------------------------------------------
__global__ void __launch_bounds__(THREADS, 1)
router_kernel(const float* __restrict__ x,
              const float* __restrict__ W,
              const float* __restrict__ b,
              float* __restrict__ out) {
    // smem: [buf0_x][buf1_x][buf0_w][buf1_w], each 64 x 36 floats (2304)
    __shared__ __align__(16) float smem[4 * TM * XS_STRIDE];  // 36 KB

    const int tid = threadIdx.x;
    const int tx  = tid & 15;          // expert group (4 experts)
    const int ty  = tid >> 4;          // row group (4 rows)
    const int m0  = blockIdx.x * TM;

    const uint32_t sbase = smem_u32(smem);

    // --- cp.async tile loader: 2 float4 per array per thread -----------------
    const int lr  = tid >> 3;          // 0..31 (rows, second half at +32)
    const int lc4 = (tid & 7) * 4;     // float offset within k-tile

    auto issue_tile = [&](int buf, int t) {
        const int k0 = t * KT;
        const float* gx = x + (size_t)(m0 + lr) * DIM + k0 + lc4;
        const float* gw = W + (size_t)lr * DIM + k0 + lc4;
        uint32_t sx = sbase + (uint32_t)((buf * TM * XS_STRIDE)
                                         + lr * XS_STRIDE + lc4) * 4u;
        uint32_t sw = sbase + (uint32_t)((2 * TM * XS_STRIDE)
                                         + (buf * TM * XS_STRIDE)
                                         + lr * XS_STRIDE + lc4) * 4u;
        cp16(sx, gx);
        cp16(sw, gw);
        cp16(sx + 32u * XS_STRIDE * 4u, gx + (size_t)32 * DIM);
        cp16(sw + 32u * XS_STRIDE * 4u, gw + (size_t)32 * DIM);
    };

    // Accumulators: [row][expert][k-pair], packed f32x2 (even-k lane, odd-k lane)
    unsigned long long acc[4][4][2];
#pragma unroll
    for (int i = 0; i < 4; ++i)
#pragma unroll
        for (int j = 0; j < 4; ++j) {
            acc[i][j][0] = 0ull;
            acc[i][j][1] = 0ull;
        }

    // Prologue: prefetch tile 0
    issue_tile(0, 0);
    cp_commit();

    for (int t = 0; t < NTILES; ++t) {
        if (t + 1 < NTILES) {
            issue_tile((t + 1) & 1, t + 1);
            cp_commit();
            cp_wait<1>();            // tile t complete, tile t+1 in flight
        } else {
            cp_wait<0>();
        }
        __syncthreads();

        const float* xb = smem + (t & 1) * TM * XS_STRIDE;
        const float* wb = smem + 2 * TM * XS_STRIDE + (t & 1) * TM * XS_STRIDE;

#pragma unroll
        for (int kk = 0; kk < KT / 4; ++kk) {
            unsigned long long xa[4][2], wa[4][2];
#pragma unroll
            for (int i = 0; i < 4; ++i) {
                ulonglong2 v = *reinterpret_cast<const ulonglong2*>(
                    xb + (4 * ty + i) * XS_STRIDE + 4 * kk);
                xa[i][0] = v.x; xa[i][1] = v.y;
            }
#pragma unroll
            for (int j = 0; j < 4; ++j) {
                ulonglong2 v = *reinterpret_cast<const ulonglong2*>(
                    wb + (4 * tx + j) * XS_STRIDE + 4 * kk);
                wa[j][0] = v.x; wa[j][1] = v.y;
            }
#pragma unroll
            for (int i = 0; i < 4; ++i)
#pragma unroll
                for (int j = 0; j < 4; ++j) {
                    fma2(acc[i][j][0], xa[i][0], wa[j][0]);
                    fma2(acc[i][j][1], xa[i][1], wa[j][1]);
                }
        }
        __syncthreads();   // protect buffer t&1 before t+1's issue overwrites peer
    }

    // --- Epilogue: logits -> smem (stride 65 => conflict-free row scans) -----
    float* lg = smem;      // 64 x 65 floats = 16.6 KB, fits in the 36 KB buffer
#pragma unroll
    for (int j = 0; j < 4; ++j) {
        const float bias = b[4 * tx + j];
#pragma unroll
        for (int i = 0; i < 4; ++i) {
            float v = u64_lo(acc[i][j][0]) + u64_hi(acc[i][j][0])
                    + u64_lo(acc[i][j][1]) + u64_hi(acc[i][j][1]) + bias;
            lg[(4 * ty + i) * 65 + (4 * tx + j)] = v;
        }
    }
    __syncthreads();

    // --- Softmax + top-2 per row (one thread per row) -------------------------
    if (tid < TM) {
        const float* row = lg + tid * 65;
        float v1 = -3.4e38f, v2 = -3.4e38f;
        int   i1 = 0,        i2 = 0;
#pragma unroll
        for (int e = 0; e < NEXP; ++e) {
            float v = row[e];
            if (v > v1) { v2 = v1; i2 = i1; v1 = v; i1 = e; }
            else if (v > v2) { v2 = v; i2 = e; }
        }
        float sum = 0.0f;
#pragma unroll
        for (int e = 0; e < NEXP; ++e)
            sum += expf(row[e] - v1);
        const float inv = 1.0f / sum;

        const int gr = m0 + tid;
        out[gr * TOPK + 0] = (float)i1;
        out[gr * TOPK + 1] = (float)i2;
        out[N_ROWS * TOPK + gr * TOPK + 0] = inv;                    // exp(0)/sum
        out[N_ROWS * TOPK + gr * TOPK + 1] = expf(v2 - v1) * inv;
    }
}

// ---------------------------------------------------------------------------
extern "C" void kernel_launch(void* const* d_in, const int* in_sizes, int n_in,
                              void* d_out, int out_size) {
    const float* x = (const float*)d_in[0];   // [N, D] fp32
    const float* W = (const float*)d_in[1];   // [E, D] fp32
    const float* b = (const float*)d_in[2];   // [E]    fp32
    (void)in_sizes; (void)n_in; (void)out_size;  // k is fixed at 2

    float* out = (float*)d_out;
    router_kernel<<<N_ROWS / TM, THREADS>>>(x, W, b, out);
}

// round 7
// speedup vs baseline: 1.0014x; 1.0014x over previous
#include <cuda_runtime.h>
#include <cstdint>

// Problem constants (fixed by the reference: N=8192, D=4096, E=64, K=2)
#define N_ROWS   8192
#define DIM      4096
#define NEXP     64
#define TOPK     2

// Tiling
#define TM       64            // rows per CTA
#define KT       32            // k-tile depth
#define XS_STRIDE 36           // 32 + 4 pad (keeps float4 alignment, dodges bank conflicts)
#define THREADS  256
#define NTILES   (DIM / KT)    // 128

// ---------------------------------------------------------------------------
// PTX helpers
// ---------------------------------------------------------------------------
__device__ __forceinline__ void fma2(unsigned long long& acc,
                                     unsigned long long a,
                                     unsigned long long b) {
    // packed f32x2 FMA: acc.lo += a.lo*b.lo ; acc.hi += a.hi*b.hi
    asm volatile("fma.rn.f32x2 %0, %1, %2, %0;" : "+l"(acc) : "l"(a), "l"(b));
}

__device__ __forceinline__ void cp16(uint32_t smem_addr, const void* gptr) {
    asm volatile("cp.async.ca.shared.global [%0], [%1], 16;"
                 :: "r"(smem_addr), "l"(gptr));
}
__device__ __forceinline__ void cp_commit() {
    asm volatile("cp.async.commit_group;");
}
template <int N>
__device__ __forceinline__ void cp_wait() {
    asm volatile("cp.async.wait_group %0;" :: "n"(N));
}

__device__ __forceinline__ uint32_t smem_u32(const void* p) {
    uint32_t r;
    asm("{ .reg .u64 t; cvta.to.shared.u64 t, %1; cvt.u32.u64 %0, t; }"
        : "=r"(r) : "l"(p));
    return r;
}

__device__ __forceinline__ float u64_lo(unsigned long long a) {
    return __uint_as_float((uint32_t)(a & 0xffffffffull));
}
__device__ __forceinline__ float u64_hi(unsigned long long a) {
    return __uint_as_float((uint32_t)(a >> 32));
}

// ---------------------------------------------------------------------------
// Fused kernel: logits GEMM (fp32, FFMA2) + bias + softmax + top-2
// out layout: [0 : N*K)          top-2 indices (as float)
//             [N*K : 2*N*K)      top-2 softmax weights
// ---------------------------------------------------------------------------
__global__ void __launch_bounds__(THREADS, 1)
router_kernel(const float* __restrict__ x,
              const float* __restrict__ W,
              const float* __restrict__ b,
              float* __restrict__ out) {
    // smem: [buf0_x][buf1_x][buf0_w][buf1_w], each 64 x 36 floats (2304)
    __shared__ __align__(16) float smem[4 * TM * XS_STRIDE];  // 36 KB

    const int tid = threadIdx.x;
    const int tx  = tid & 15;          // expert group (4 experts)
    const int ty  = tid >> 4;          // row group (4 rows)
    const int m0  = blockIdx.x * TM;

    const uint32_t sbase = smem_u32(smem);

    // --- cp.async tile loader: 2 float4 per array per thread -----------------
    const int lr  = tid >> 3;          // 0..31 (rows, second half at +32)
    const int lc4 = (tid & 7) * 4;     // float offset within k-tile

    auto issue_tile = [&](int buf, int t) {
        const int k0 = t * KT;
        const float* gx = x + (size_t)(m0 + lr) * DIM + k0 + lc4;
        const float* gw = W + (size_t)lr * DIM + k0 + lc4;
        uint32_t sx = sbase + (uint32_t)((buf * TM * XS_STRIDE)
                                         + lr * XS_STRIDE + lc4) * 4u;
        uint32_t sw = sbase + (uint32_t)((2 * TM * XS_STRIDE)
                                         + (buf * TM * XS_STRIDE)
                                         + lr * XS_STRIDE + lc4) * 4u;
        cp16(sx, gx);
        cp16(sw, gw);
        cp16(sx + 32u * XS_STRIDE * 4u, gx + (size_t)32 * DIM);
        cp16(sw + 32u * XS_STRIDE * 4u, gw + (size_t)32 * DIM);
    };

    // Accumulators: [row][expert][k-pair], packed f32x2 (even-k lane, odd-k lane)
    unsigned long long acc[4][4][2];
#pragma unroll
    for (int i = 0; i < 4; ++i)
#pragma unroll
        for (int j = 0; j < 4; ++j) {
            acc[i][j][0] = 0ull;
            acc[i][j][1] = 0ull;
        }

    // Prologue: prefetch tile 0
    issue_tile(0, 0);
    cp_commit();

    for (int t = 0; t < NTILES; ++t) {
        if (t + 1 < NTILES) {
            issue_tile((t + 1) & 1, t + 1);
            cp_commit();
            cp_wait<1>();            // tile t complete, tile t+1 in flight
        } else {
            cp_wait<0>();
        }
        __syncthreads();

        const float* xb = smem + (t & 1) * TM * XS_STRIDE;
        const float* wb = smem + 2 * TM * XS_STRIDE + (t & 1) * TM * XS_STRIDE;

#pragma unroll
        for (int kk = 0; kk < KT / 4; ++kk) {
            unsigned long long xa[4][2], wa[4][2];
#pragma unroll
            for (int i = 0; i < 4; ++i) {
                ulonglong2 v = *reinterpret_cast<const ulonglong2*>(
                    xb + (4 * ty + i) * XS_STRIDE + 4 * kk);
                xa[i][0] = v.x; xa[i][1] = v.y;
            }
#pragma unroll
            for (int j = 0; j < 4; ++j) {
                ulonglong2 v = *reinterpret_cast<const ulonglong2*>(
                    wb + (4 * tx + j) * XS_STRIDE + 4 * kk);
                wa[j][0] = v.x; wa[j][1] = v.y;
            }
#pragma unroll
            for (int i = 0; i < 4; ++i)
#pragma unroll
                for (int j = 0; j < 4; ++j) {
                    fma2(acc[i][j][0], xa[i][0], wa[j][0]);
                    fma2(acc[i][j][1], xa[i][1], wa[j][1]);
                }
        }
        __syncthreads();   // protect buffer t&1 before t+1's issue overwrites peer
    }

    // --- Epilogue: logits -> smem (stride 65 => conflict-free row scans) -----
    float* lg = smem;      // 64 x 65 floats = 16.6 KB, fits in the 36 KB buffer
#pragma unroll
    for (int j = 0; j < 4; ++j) {
        const float bias = b[4 * tx + j];
#pragma unroll
        for (int i = 0; i < 4; ++i) {
            float v = u64_lo(acc[i][j][0]) + u64_hi(acc[i][j][0])
                    + u64_lo(acc[i][j][1]) + u64_hi(acc[i][j][1]) + bias;
            lg[(4 * ty + i) * 65 + (4 * tx + j)] = v;
        }
    }
    __syncthreads();

    // --- Softmax + top-2 per row (one thread per row) -------------------------
    if (tid < TM) {
        const float* row = lg + tid * 65;
        float v1 = -3.4e38f, v2 = -3.4e38f;
        int   i1 = 0,        i2 = 0;
#pragma unroll
        for (int e = 0; e < NEXP; ++e) {
            float v = row[e];
            if (v > v1) { v2 = v1; i2 = i1; v1 = v; i1 = e; }
            else if (v > v2) { v2 = v; i2 = e; }
        }
        float sum = 0.0f;
#pragma unroll
        for (int e = 0; e < NEXP; ++e)
            sum += expf(row[e] - v1);
        const float inv = 1.0f / sum;

        const int gr = m0 + tid;
        out[gr * TOPK + 0] = (float)i1;
        out[gr * TOPK + 1] = (float)i2;
        out[N_ROWS * TOPK + gr * TOPK + 0] = inv;                    // exp(0)/sum
        out[N_ROWS * TOPK + gr * TOPK + 1] = expf(v2 - v1) * inv;
    }
}

// ---------------------------------------------------------------------------
extern "C" void kernel_launch(void* const* d_in, const int* in_sizes, int n_in,
                              void* d_out, int out_size) {
    const float* x = (const float*)d_in[0];   // [N, D] fp32
    const float* W = (const float*)d_in[1];   // [E, D] fp32
    const float* b = (const float*)d_in[2];   // [E]    fp32
    (void)in_sizes; (void)n_in; (void)out_size;  // k is fixed at 2

    float* out = (float*)d_out;
    router_kernel<<<N_ROWS / TM, THREADS>>>(x, W, b, out);
}